// round 3
// baseline (speedup 1.0000x reference)
#include <cuda_runtime.h>
#include <math.h>

// SVRaster: 4096 rays vs 16^3 regular voxel grid on [-1,1]^3.
//
// Incremental DDA: maintain per-axis entry crossings (lx,ly,lz) and exit
// crossings (nx,ny,nz), each computed DIRECTLY as (plane - o) * inv with
// plane = i*0.125 - 1 (exact fp32 dyadic) -- bit-identical to the
// reference's per-voxel slab test values (ctr +/- half == i*0.125 - 1
// exactly). Hit test per cell: min(nx,ny,nz) > max(lx,ly,lz,0).
// Cells are visited in increasing t_near order == reference argsort order.
//
// Phase A records hits (v, tn, tf) to local arrays; Phase B composites with
// batched loads (indices known up-front -> high MLP). Single kernel.

#define GRID_N   16
#define CELL     0.125f
#define INV_CELL 8.0f
#define BMIN     (-1.0f)
#define MAX_HITS 100
#define MAX_REC  80

__device__ __forceinline__ float safe_dir(float d) {
    return (fabsf(d) < 1e-8f) ? ((d >= 0.0f) ? 1e-8f : -1e-8f) : d;
}

__global__ void __launch_bounds__(32)
svraster_kernel(const float* __restrict__ ro,
                const float* __restrict__ rd,
                const float* __restrict__ vdens,
                const float* __restrict__ vcol,
                float* __restrict__ out,
                int R)
{
    int r = blockIdx.x * blockDim.x + threadIdx.x;
    if (r >= R) return;

    float* out_rgb = out;
    float* out_dep = out + (size_t)3 * R;
    float* out_cnt = out + (size_t)4 * R;
    float* out_idx = out + (size_t)5 * R + (size_t)r * MAX_HITS;

    const float ox = ro[3 * r + 0], oy = ro[3 * r + 1], oz = ro[3 * r + 2];
    const float dx = rd[3 * r + 0], dy = rd[3 * r + 1], dz = rd[3 * r + 2];

    const float invx = 1.0f / safe_dir(dx);
    const float invy = 1.0f / safe_dir(dy);
    const float invz = 1.0f / safe_dir(dz);

    // Scene box slab (box = [-1,1]^3).
    float tx0 = (BMIN - ox) * invx, tx1 = (1.0f - ox) * invx;
    float ty0 = (BMIN - oy) * invy, ty1 = (1.0f - oy) * invy;
    float tz0 = (BMIN - oz) * invz, tz1 = (1.0f - oz) * invz;
    float tEnter = fmaxf(fmaxf(fminf(tx0, tx1), fminf(ty0, ty1)), fminf(tz0, tz1));
    float tExit  = fminf(fminf(fmaxf(tx0, tx1), fmaxf(ty0, ty1)), fmaxf(tz0, tz1));
    tEnter = fmaxf(tEnter, 0.0f);

    // ---- Phase A: register-only incremental DDA, record hits ----
    int   hv [MAX_REC];
    float htn[MAX_REC];
    float htf[MAX_REC];
    int count = 0;

    if (tExit > tEnter) {
        float px = ox + dx * tEnter;
        float py = oy + dy * tEnter;
        float pz = oz + dz * tEnter;
        int cix = min(GRID_N - 1, max(0, (int)floorf((px - BMIN) * INV_CELL)));
        int ciy = min(GRID_N - 1, max(0, (int)floorf((py - BMIN) * INV_CELL)));
        int ciz = min(GRID_N - 1, max(0, (int)floorf((pz - BMIN) * INV_CELL)));

        const int sx = (invx >= 0.0f) ? 1 : -1;
        const int sy = (invy >= 0.0f) ? 1 : -1;
        const int sz = (invz >= 0.0f) ? 1 : -1;
        const float scx = (sx > 0) ? CELL : -CELL;
        const float scy = (sy > 0) ? CELL : -CELL;
        const float scz = (sz > 0) ? CELL : -CELL;
        const int ex = (sx > 0) ? 1 : 0;   // exit-side plane offset
        const int ey = (sy > 0) ? 1 : 0;
        const int ez = (sz > 0) ? 1 : 0;

        // Exit crossings of the entry cell (direct arithmetic).
        float nx = (fmaf((float)(cix + ex), CELL, BMIN) - ox) * invx;
        float ny = (fmaf((float)(ciy + ey), CELL, BMIN) - oy) * invy;
        float nz = (fmaf((float)(ciz + ez), CELL, BMIN) - oz) * invz;

        // Boundary-behind correction: floor() may land one cell short.
        if (nx < tEnter) cix += sx;
        if (ny < tEnter) ciy += sy;
        if (nz < tEnter) ciz += sz;
        cix = min(GRID_N - 1, max(0, cix));
        ciy = min(GRID_N - 1, max(0, ciy));
        ciz = min(GRID_N - 1, max(0, ciz));

        // (Re)compute plane coords + crossings from the final entry cell.
        float pxp = fmaf((float)(cix + ex), CELL, BMIN);
        float pyp = fmaf((float)(ciy + ey), CELL, BMIN);
        float pzp = fmaf((float)(ciz + ez), CELL, BMIN);
        nx = (pxp - ox) * invx;
        ny = (pyp - oy) * invy;
        nz = (pzp - oz) * invz;
        float lx = (fmaf((float)(cix + 1 - ex), CELL, BMIN) - ox) * invx;
        float ly = (fmaf((float)(ciy + 1 - ey), CELL, BMIN) - oy) * invy;
        float lz = (fmaf((float)(ciz + 1 - ez), CELL, BMIN) - oz) * invz;

        #pragma unroll 1
        for (int it = 0; it < MAX_REC; ++it) {
            float tn = fmaxf(fmaxf(lx, ly), fmaxf(lz, 0.0f));
            float tf = fminf(fminf(nx, ny), nz);

            if (tf > tn) {
                hv [count] = (cix * GRID_N + ciy) * GRID_N + ciz;
                htn[count] = tn;
                htf[count] = tf;
                ++count;
            }

            // Step the axis with the smallest exit crossing.
            if (nx <= ny && nx <= nz) {
                cix += sx;
                if ((unsigned)cix >= GRID_N) break;
                lx = nx; pxp += scx; nx = (pxp - ox) * invx;
            } else if (ny <= nz) {
                ciy += sy;
                if ((unsigned)ciy >= GRID_N) break;
                ly = ny; pyp += scy; ny = (pyp - oy) * invy;
            } else {
                ciz += sz;
                if ((unsigned)ciz >= GRID_N) break;
                lz = nz; pzp += scz; nz = (pzp - oz) * invz;
            }
        }
    }

    // Zero-fill idx100 with vectorized stores (row is 400B, 16B-aligned).
    {
        float4 z4 = make_float4(0.0f, 0.0f, 0.0f, 0.0f);
        float4* oi4 = (float4*)out_idx;
        #pragma unroll
        for (int j = 0; j < MAX_HITS / 4; ++j) oi4[j] = z4;
    }

    // ---- Phase B: composite (batched loads; indices known up-front) ----
    float T = 1.0f, cr = 0.0f, cg = 0.0f, cb = 0.0f, dep = 0.0f;

    #pragma unroll 4
    for (int i = 0; i < count; ++i) {
        int v = hv[i];
        float sigma = expf(__ldg(&vdens[v]));
        float c0 = __ldg(&vcol[3 * v + 0]);
        float c1 = __ldg(&vcol[3 * v + 1]);
        float c2 = __ldg(&vcol[3 * v + 2]);
        float tn = htn[i], tf = htf[i];
        float dt = tf - tn;
        float alpha = 1.0f - expf(-sigma * dt);
        float w = T * alpha;
        cr  += w * c0;
        cg  += w * c1;
        cb  += w * c2;
        dep += w * 0.5f * (tn + tf);
        T *= (1.0f - alpha + 1e-10f);
        if (i < MAX_HITS) out_idx[i] = (float)v;
    }

    out_rgb[3 * r + 0] = cr;
    out_rgb[3 * r + 1] = cg;
    out_rgb[3 * r + 2] = cb;
    out_dep[r] = dep;
    out_cnt[r] = (float)count;
}

extern "C" void kernel_launch(void* const* d_in, const int* in_sizes, int n_in,
                              void* d_out, int out_size)
{
    const float* ro    = (const float*)d_in[0];
    const float* rd    = (const float*)d_in[1];
    const float* vdens = (const float*)d_in[4];
    const float* vcol  = (const float*)d_in[5];
    float* out = (float*)d_out;

    int R = in_sizes[0] / 3;
    int threads = 32;
    int blocks = (R + threads - 1) / threads;
    svraster_kernel<<<blocks, threads>>>(ro, rd, vdens, vcol, out, R);
}

// round 4
// speedup vs baseline: 1.2776x; 1.2776x over previous
#include <cuda_runtime.h>
#include <math.h>

// SVRaster: 4096 rays vs 16^3 regular voxel grid on [-1,1]^3.
//
// Branchless incremental DDA. Per-axis entry/exit crossings computed
// DIRECTLY as (plane - o) * inv with plane = i*0.125 - 1 (exact fp32
// dyadic, bit-identical to the reference's ctr +/- half slab values).
// Cells visited in increasing t_near order == reference argsort order.
// Hit record is UNCONDITIONAL store to slot `count` + conditional count
// increment -> no predicated arms, no divergent branches in the loop.
// Phase B composites from shared-memory hit list with unrolled loads.

#define GRID_N   16
#define CELL     0.125f
#define INV_CELL 8.0f
#define BMIN     (-1.0f)
#define MAX_HITS 100
#define MAX_REC  48
#define LOG2E    1.4426950408889634f

__device__ __forceinline__ float safe_dir(float d) {
    return (fabsf(d) < 1e-8f) ? ((d >= 0.0f) ? 1e-8f : -1e-8f) : d;
}

__global__ void __launch_bounds__(32)
svraster_kernel(const float* __restrict__ ro,
                const float* __restrict__ rd,
                const float* __restrict__ vdens,
                const float* __restrict__ vcol,
                float* __restrict__ out,
                int R)
{
    // Lane-strided hit list: index [i*32 + lane] -> conflict-free.
    __shared__ int   sh_v [MAX_REC * 32];
    __shared__ float sh_tn[MAX_REC * 32];
    __shared__ float sh_tf[MAX_REC * 32];

    const int tid = threadIdx.x;
    const int r = blockIdx.x * 32 + tid;
    if (r >= R) return;   // R is a multiple of 32; guard is uniform.

    float* out_rgb = out;
    float* out_dep = out + (size_t)3 * R;
    float* out_cnt = out + (size_t)4 * R;
    float* out_idx = out + (size_t)5 * R + (size_t)r * MAX_HITS;

    const float ox = ro[3 * r + 0], oy = ro[3 * r + 1], oz = ro[3 * r + 2];
    const float dx = rd[3 * r + 0], dy = rd[3 * r + 1], dz = rd[3 * r + 2];

    const float invx = 1.0f / safe_dir(dx);
    const float invy = 1.0f / safe_dir(dy);
    const float invz = 1.0f / safe_dir(dz);

    // Scene box slab (box = [-1,1]^3).
    float tx0 = (BMIN - ox) * invx, tx1 = (1.0f - ox) * invx;
    float ty0 = (BMIN - oy) * invy, ty1 = (1.0f - oy) * invy;
    float tz0 = (BMIN - oz) * invz, tz1 = (1.0f - oz) * invz;
    float tEnter = fmaxf(fmaxf(fminf(tx0, tx1), fminf(ty0, ty1)), fminf(tz0, tz1));
    float tExit  = fminf(fminf(fmaxf(tx0, tx1), fmaxf(ty0, ty1)), fmaxf(tz0, tz1));
    tEnter = fmaxf(tEnter, 0.0f);

    bool alive = (tExit > tEnter);
    int count = 0;

    // ---- Phase A setup (computed unconditionally; only used if alive) ----
    float px = ox + dx * tEnter;
    float py = oy + dy * tEnter;
    float pz = oz + dz * tEnter;
    int cix = min(GRID_N - 1, max(0, (int)floorf((px - BMIN) * INV_CELL)));
    int ciy = min(GRID_N - 1, max(0, (int)floorf((py - BMIN) * INV_CELL)));
    int ciz = min(GRID_N - 1, max(0, (int)floorf((pz - BMIN) * INV_CELL)));

    const int sx = (invx >= 0.0f) ? 1 : -1;
    const int sy = (invy >= 0.0f) ? 1 : -1;
    const int sz = (invz >= 0.0f) ? 1 : -1;
    const float scx = (sx > 0) ? CELL : -CELL;
    const float scy = (sy > 0) ? CELL : -CELL;
    const float scz = (sz > 0) ? CELL : -CELL;
    const int ex = (sx > 0) ? 1 : 0;
    const int ey = (sy > 0) ? 1 : 0;
    const int ez = (sz > 0) ? 1 : 0;

    // Exit crossings of the tentative entry cell.
    float nx = (fmaf((float)(cix + ex), CELL, BMIN) - ox) * invx;
    float ny = (fmaf((float)(ciy + ey), CELL, BMIN) - oy) * invy;
    float nz = (fmaf((float)(ciz + ez), CELL, BMIN) - oz) * invz;

    // Boundary-behind correction: floor() may land one cell short.
    cix = min(GRID_N - 1, max(0, cix + ((nx < tEnter) ? sx : 0)));
    ciy = min(GRID_N - 1, max(0, ciy + ((ny < tEnter) ? sy : 0)));
    ciz = min(GRID_N - 1, max(0, ciz + ((nz < tEnter) ? sz : 0)));

    float pxp = fmaf((float)(cix + ex), CELL, BMIN);
    float pyp = fmaf((float)(ciy + ey), CELL, BMIN);
    float pzp = fmaf((float)(ciz + ez), CELL, BMIN);
    nx = (pxp - ox) * invx;
    ny = (pyp - oy) * invy;
    nz = (pzp - oz) * invz;
    float lx = (fmaf((float)(cix + 1 - ex), CELL, BMIN) - ox) * invx;
    float ly = (fmaf((float)(ciy + 1 - ey), CELL, BMIN) - oy) * invy;
    float lz = (fmaf((float)(ciz + 1 - ez), CELL, BMIN) - oz) * invz;

    // ---- Phase A: branchless DDA loop ----
    #pragma unroll 1
    for (int it = 0; it < 64; ++it) {
        if (!__ballot_sync(0xffffffffu, alive)) break;

        float tn = fmaxf(fmaxf(lx, ly), fmaxf(lz, 0.0f));
        float tf = fminf(fminf(nx, ny), nz);
        bool hit = (tf > tn) && alive;

        // Unconditional record into slot `count`; advance only on hit.
        int slot = count * 32 + tid;
        sh_v [slot] = (cix * GRID_N + ciy) * GRID_N + ciz;
        sh_tn[slot] = tn;
        sh_tf[slot] = tf;
        count += hit ? 1 : 0;

        // Branchless step: axis with smallest exit crossing (x, then y, then z).
        bool stepx = (nx <= ny) && (nx <= nz);
        bool stepy = !stepx && (ny <= nz);
        bool stepz = !stepx && !stepy;

        cix += stepx ? sx : 0;
        ciy += stepy ? sy : 0;
        ciz += stepz ? sz : 0;

        lx = stepx ? nx : lx;
        ly = stepy ? ny : ly;
        lz = stepz ? nz : lz;

        pxp = stepx ? (pxp + scx) : pxp;
        pyp = stepy ? (pyp + scy) : pyp;
        pzp = stepz ? (pzp + scz) : pzp;

        nx = stepx ? ((pxp - ox) * invx) : nx;
        ny = stepy ? ((pyp - oy) * invy) : ny;
        nz = stepz ? ((pzp - oz) * invz) : nz;

        alive = alive && ((unsigned)cix < GRID_N)
                      && ((unsigned)ciy < GRID_N)
                      && ((unsigned)ciz < GRID_N);
    }

    // Zero-fill idx100 with vectorized stores (row is 400B, 16B-aligned).
    {
        float4 z4 = make_float4(0.0f, 0.0f, 0.0f, 0.0f);
        float4* oi4 = (float4*)out_idx;
        #pragma unroll
        for (int j = 0; j < MAX_HITS / 4; ++j) oi4[j] = z4;
    }

    // ---- Phase B: composite (hit list known -> pipelined loads) ----
    float T = 1.0f, cr = 0.0f, cg = 0.0f, cb = 0.0f, dep = 0.0f;

    #pragma unroll 4
    for (int i = 0; i < count; ++i) {
        int slot = i * 32 + tid;
        int v = sh_v[slot];
        float tn = sh_tn[slot], tf = sh_tf[slot];
        float sigma = __expf(__ldg(&vdens[v]));
        float c0 = __ldg(&vcol[3 * v + 0]);
        float c1 = __ldg(&vcol[3 * v + 1]);
        float c2 = __ldg(&vcol[3 * v + 2]);
        float dt = tf - tn;
        float alpha = 1.0f - __expf(-sigma * dt);
        float w = T * alpha;
        cr  += w * c0;
        cg  += w * c1;
        cb  += w * c2;
        dep += w * 0.5f * (tn + tf);
        T *= (1.0f - alpha + 1e-10f);
        out_idx[i] = (float)v;     // count <= 46 < MAX_HITS always
    }

    out_rgb[3 * r + 0] = cr;
    out_rgb[3 * r + 1] = cg;
    out_rgb[3 * r + 2] = cb;
    out_dep[r] = dep;
    out_cnt[r] = (float)count;
}

extern "C" void kernel_launch(void* const* d_in, const int* in_sizes, int n_in,
                              void* d_out, int out_size)
{
    const float* ro    = (const float*)d_in[0];
    const float* rd    = (const float*)d_in[1];
    const float* vdens = (const float*)d_in[4];
    const float* vcol  = (const float*)d_in[5];
    float* out = (float*)d_out;

    int R = in_sizes[0] / 3;
    int threads = 32;
    int blocks = (R + threads - 1) / threads;
    svraster_kernel<<<blocks, threads>>>(ro, rd, vdens, vcol, out, R);
}

// round 5
// speedup vs baseline: 1.6090x; 1.2594x over previous
#include <cuda_runtime.h>
#include <math.h>

// SVRaster: 4096 rays vs 16^3 regular voxel grid on [-1,1]^3.
//
// 16 threads per ray. Lane j owns the j-th slab (traversal order) along the
// ray's dominant axis D; since |dU|,|dV| <= |dD| a slab contains <= 5 visited
// cells, enumerated by a tiny 2D mini-DDA. Every cell is tested with the
// EXACT reference slab arithmetic (planes i*0.125-1 are exact fp32 ==
// ctr +/- half), so extra candidate cells are harmlessly rejected and the
// hit set matches the reference exactly. Hits are globally tn-ordered by
// (slab order, walk order). Compositing uses the linearity of volume
// rendering in incoming transmittance: local composite with T=1, then a
// width-16 shuffle prefix-product supplies each lane's true T0.

#define GN       16
#define CELL     0.125f
#define BMIN     (-1.0f)
#define MAX_HITS 100
#define GROUP    16
#define BLOCK    128
#define LOC_MAX  8

__device__ __forceinline__ float safe_dir(float d) {
    return (fabsf(d) < 1e-8f) ? ((d >= 0.0f) ? 1e-8f : -1e-8f) : d;
}

__global__ void __launch_bounds__(BLOCK)
svraster_kernel(const float* __restrict__ ro,
                const float* __restrict__ rd,
                const float* __restrict__ vdens,
                const float* __restrict__ vcol,
                float* __restrict__ out,
                int R)
{
    __shared__ int sh_v[LOC_MAX * BLOCK];   // slot-major: conflict-free

    const unsigned FULL = 0xffffffffu;
    const int tid = threadIdx.x;
    const int j   = tid & (GROUP - 1);                     // lane in ray group
    const int r   = (blockIdx.x * BLOCK + tid) >> 4;       // ray id
    // Grid covers R*16 threads exactly (R multiple of 8); no early return.

    const float ox = ro[3 * r + 0], oy = ro[3 * r + 1], oz = ro[3 * r + 2];
    const float dxr = rd[3 * r + 0], dyr = rd[3 * r + 1], dzr = rd[3 * r + 2];

    const float ivx = 1.0f / safe_dir(dxr);
    const float ivy = 1.0f / safe_dir(dyr);
    const float ivz = 1.0f / safe_dir(dzr);

    // Scene-box slab (exact same planes as grid faces).
    float tx0 = (BMIN - ox) * ivx, tx1 = (1.0f - ox) * ivx;
    float ty0 = (BMIN - oy) * ivy, ty1 = (1.0f - oy) * ivy;
    float tz0 = (BMIN - oz) * ivz, tz1 = (1.0f - oz) * ivz;
    float tEnter = fmaxf(fmaxf(fminf(tx0, tx1), fminf(ty0, ty1)), fminf(tz0, tz1));
    float tExit  = fminf(fminf(fmaxf(tx0, tx1), fmaxf(ty0, ty1)), fmaxf(tz0, tz1));
    tEnter = fmaxf(tEnter, 0.0f);

    // Dominant axis D = argmax |d|;  (D,U,V) permutation:
    // axis0: (x,y,z)  axis1: (y,x,z)  axis2: (z,x,y)
    float adx = fabsf(dxr), ady = fabsf(dyr), adz = fabsf(dzr);
    int axis = (adx >= ady && adx >= adz) ? 0 : ((ady >= adz) ? 1 : 2);

    float oD = (axis == 0) ? ox : ((axis == 1) ? oy : oz);
    float oU = (axis == 0) ? oy : ox;
    float oV = (axis == 2) ? oy : oz;
    float iD = (axis == 0) ? ivx : ((axis == 1) ? ivy : ivz);
    float iU = (axis == 0) ? ivy : ivx;
    float iV = (axis == 2) ? ivy : ivz;
    float dUr = (axis == 0) ? dyr : dxr;
    float dVr = (axis == 2) ? dyr : dzr;

    const int sD = (iD >= 0.0f) ? 1 : -1;
    const int sU = (iU >= 0.0f) ? 1 : -1;
    const int sV = (iV >= 0.0f) ? 1 : -1;
    const int exU = (sU > 0) ? 1 : 0;
    const int exV = (sV > 0) ? 1 : 0;

    // Lane j -> slab k in traversal order.
    const int k = (sD > 0) ? j : (GN - 1 - j);

    // Exact D-axis crossings of slab k (== reference per-voxel D slab values).
    float pk0 = fmaf((float)k,       CELL, BMIN);
    float pk1 = fmaf((float)(k + 1), CELL, BMIN);
    float tA = (pk0 - oD) * iD;
    float tB = (pk1 - oD) * iD;
    float lDk = fminf(tA, tB);
    float nDk = fmaxf(tA, tB);

    float w0 = fmaxf(lDk, tEnter);
    float w1 = fminf(nDk, tExit);
    bool alive = (w1 > w0);

    // Starting U/V cells at t = w0 (+ both-direction boundary corrections;
    // extra candidate cells are harmless, missed cells are not).
    float pu = fmaf(dUr, w0, oU);
    float pv = fmaf(dVr, w0, oV);
    int u = (int)floorf((pu - BMIN) * 8.0f);
    int v = (int)floorf((pv - BMIN) * 8.0f);

    float lu = (fmaf((float)(u + 1 - exU), CELL, BMIN) - oU) * iU;
    float nu = (fmaf((float)(u + exU),     CELL, BMIN) - oU) * iU;
    if      (nu < w0) u += sU;       // floor undershot: advance
    else if (lu > w0) u -= sU;       // floor overshot: include predecessor
    lu = (fmaf((float)(u + 1 - exU), CELL, BMIN) - oU) * iU;
    nu = (fmaf((float)(u + exU),     CELL, BMIN) - oU) * iU;

    float lv = (fmaf((float)(v + 1 - exV), CELL, BMIN) - oV) * iV;
    float nv = (fmaf((float)(v + exV),     CELL, BMIN) - oV) * iV;
    if      (nv < w0) v += sV;
    else if (lv > w0) v -= sV;
    lv = (fmaf((float)(v + 1 - exV), CELL, BMIN) - oV) * iV;
    nv = (fmaf((float)(v + exV),     CELL, BMIN) - oV) * iV;

    // ---- per-slab mini-DDA + local composite (T starts at 1) ----
    float Tl = 1.0f, lr = 0.0f, lg = 0.0f, lb = 0.0f, ldep = 0.0f;
    int cnt = 0;

    #pragma unroll
    for (int it = 0; it < 8; ++it) {
        float tn = fmaxf(fmaxf(lu, lv), fmaxf(lDk, 0.0f));
        float tf = fminf(fminf(nu, nv), nDk);
        bool inb = ((unsigned)u < GN) && ((unsigned)v < GN);
        bool hit = alive && inb && (tf > tn);

        if (hit) {
            int ix = (axis == 0) ? k : u;
            int iy = (axis == 0) ? u : ((axis == 1) ? k : v);
            int iz = (axis == 2) ? k : v;
            int vox = (ix * GN + iy) * GN + iz;
            float sg = __expf(__ldg(&vdens[vox]));
            float c0 = __ldg(&vcol[3 * vox + 0]);
            float c1 = __ldg(&vcol[3 * vox + 1]);
            float c2 = __ldg(&vcol[3 * vox + 2]);
            float dt = tf - tn;
            float alpha = 1.0f - __expf(-sg * dt);
            float w = Tl * alpha;
            lr   += w * c0;
            lg   += w * c1;
            lb   += w * c2;
            ldep += w * 0.5f * (tn + tf);
            Tl   *= (1.0f - alpha + 1e-10f);
            sh_v[cnt * BLOCK + tid] = vox;
            cnt++;
        }

        // Step to next cell, or finish when the next crossing leaves window.
        float nmin = fminf(nu, nv);
        if (nmin >= w1) alive = false;
        bool stepU = (nu <= nv);
        if (alive) {
            if (stepU) { u += sU; lu = nu; nu = (fmaf((float)(u + exU), CELL, BMIN) - oU) * iU; }
            else       { v += sV; lv = nv; nv = (fmaf((float)(v + exV), CELL, BMIN) - oV) * iV; }
        }
    }

    // ---- width-16 scans: hit-count prefix sum + transmittance prefix product
    float prod = Tl;
    int   csum = cnt;
    #pragma unroll
    for (int d = 1; d < GROUP; d <<= 1) {
        float p = __shfl_up_sync(FULL, prod, d, GROUP);
        int   c = __shfl_up_sync(FULL, csum, d, GROUP);
        if (j >= d) { prod *= p; csum += c; }
    }
    float T0 = __shfl_up_sync(FULL, prod, 1, GROUP);
    if (j == 0) T0 = 1.0f;
    int base  = csum - cnt;
    int total = __shfl_sync(FULL, csum, GROUP - 1, GROUP);

    // ---- reductions: rgb/depth scale linearly with incoming T0 ----
    float sr = T0 * lr, sg2 = T0 * lg, sb = T0 * lb, sd = T0 * ldep;
    #pragma unroll
    for (int d = GROUP / 2; d > 0; d >>= 1) {
        sr  += __shfl_xor_sync(FULL, sr,  d, GROUP);
        sg2 += __shfl_xor_sync(FULL, sg2, d, GROUP);
        sb  += __shfl_xor_sync(FULL, sb,  d, GROUP);
        sd  += __shfl_xor_sync(FULL, sd,  d, GROUP);
    }

    // ---- outputs ----
    float* out_idx = out + (size_t)5 * R + (size_t)r * MAX_HITS;

    // Zero-fill idx row (25 float4 over 16 lanes), then overwrite with hits.
    float4 z4 = make_float4(0.0f, 0.0f, 0.0f, 0.0f);
    ((float4*)out_idx)[j] = z4;
    if (j < MAX_HITS / 4 - GROUP) ((float4*)out_idx)[j + GROUP] = z4;
    __syncwarp(FULL);

    for (int i = 0; i < cnt; ++i)
        out_idx[base + i] = (float)sh_v[i * BLOCK + tid];

    if (j == 0) {
        out[3 * r + 0] = sr;
        out[3 * r + 1] = sg2;
        out[3 * r + 2] = sb;
        out[(size_t)3 * R + r] = sd;
        out[(size_t)4 * R + r] = (float)total;
    }
}

extern "C" void kernel_launch(void* const* d_in, const int* in_sizes, int n_in,
                              void* d_out, int out_size)
{
    const float* ro    = (const float*)d_in[0];
    const float* rd    = (const float*)d_in[1];
    const float* vdens = (const float*)d_in[4];
    const float* vcol  = (const float*)d_in[5];
    float* out = (float*)d_out;

    int R = in_sizes[0] / 3;
    int total_threads = R * GROUP;
    int blocks = (total_threads + BLOCK - 1) / BLOCK;
    svraster_kernel<<<blocks, BLOCK>>>(ro, rd, vdens, vcol, out, R);
}